// round 10
// baseline (speedup 1.0000x reference)
#include <cuda_runtime.h>
#include <math.h>

// Reservoir step:
//   state = W @ r + W_in @ u + W_fb @ y_prev          [8192]
//   r_new = r + (DT/TAU) * (tanh(state) - r)          [8192]
//   out   = W_out @ r_new                             [32]
//
// Inputs (metadata order):
//   d_in[0] input_signal [64]        f32
//   d_in[1] W            [8192*8192] f32
//   d_in[2] W_in         [8192*64]   f32
//   d_in[3] W_fb         [8192*32]   f32
//   d_in[4] W_out        [32*8192]   f32
//   d_in[5] r            [8192]      f32
//   d_in[6] out_prev     [32]        f32
// Output: [32] f32

#define DIM_RES 8192
#define DIM_IN  64
#define DIM_OUT 32
#define LEAK    (0.1f / 10.0f)   // DT / TAU

// scratch between kernels (no cudaMalloc allowed)
__device__ float g_rnew[DIM_RES];
__device__ float g_part[DIM_OUT * 8];   // readout partials: [o][chunk]

// ---------------------------------------------------------------------------
// Kernel 1: fused  state -> tanh -> leaky update -> g_rnew
// 1024 blocks x 256 threads; one warp per row; occ 7 -> EXACT single wave
// (148 SMs x 7 = 1036 >= 1024). r staged in shared so LTS serves only W.
// Unroll 4 (16 W regs) to fit the 36-reg budget at occ 7 without spill;
// 7 blk x 8 warps x 4 lines = 224 in-flight lines/SM > ~140 needed.
// smem: 7 x 32 KB = 224 KB <= 228 KB carveout.
// ---------------------------------------------------------------------------
__global__ __launch_bounds__(256, 7)
void reservoir_update_kernel(const float* __restrict__ W,
                             const float* __restrict__ W_in,
                             const float* __restrict__ W_fb,
                             const float* __restrict__ r,
                             const float* __restrict__ u,
                             const float* __restrict__ y_prev)
{
    __shared__ float4 sr[DIM_RES / 4];   // 32 KB

    const int tid  = threadIdx.x;
    const int lane = tid & 31;
    const int wid  = tid >> 5;

    const float4* r4 = reinterpret_cast<const float4*>(r);
    #pragma unroll
    for (int t = 0; t < (DIM_RES / 4) / 256; ++t) {
        sr[tid + t * 256] = r4[tid + t * 256];
    }
    __syncthreads();

    const int row = blockIdx.x * 8 + wid;

    const float4* Wrow = reinterpret_cast<const float4*>(W + (size_t)row * DIM_RES);
    float acc = 0.0f;
    #pragma unroll 4
    for (int it = 0; it < (DIM_RES / 4) / 32; ++it) {
        const int idx = it * 32 + lane;          // coalesced 128B per warp-step
        float4 w = __ldg(&Wrow[idx]);
        float4 v = sr[idx];
        acc = fmaf(w.x, v.x, acc);
        acc = fmaf(w.y, v.y, acc);
        acc = fmaf(w.z, v.z, acc);
        acc = fmaf(w.w, v.w, acc);
    }

    // small terms: W_in[row,:] @ u (64) + W_fb[row,:] @ y_prev (32)
    {
        const float* wi = W_in + (size_t)row * DIM_IN;
        const float* wf = W_fb + (size_t)row * DIM_OUT;
        acc = fmaf(__ldg(&wi[lane]),      __ldg(&u[lane]),       acc);
        acc = fmaf(__ldg(&wi[lane + 32]), __ldg(&u[lane + 32]),  acc);
        acc = fmaf(__ldg(&wf[lane]),      __ldg(&y_prev[lane]),  acc);
    }

    #pragma unroll
    for (int off = 16; off > 0; off >>= 1)
        acc += __shfl_down_sync(0xFFFFFFFFu, acc, off);

    if (lane == 0) {
        float rv = reinterpret_cast<const float*>(sr)[row & (DIM_RES - 1)];
        float rn = rv + LEAK * (tanhf(acc) - rv);
        __stcg(&g_rnew[row], rn);    // keep in L2 for the readout
    }
}

// ---------------------------------------------------------------------------
// Kernel 2: readout partials. 256 blocks; block b -> output o=b>>3, chunk c=b&7.
// Each block reduces 1024 elems (1 float4/thread). All SMs active.
// ---------------------------------------------------------------------------
__global__ __launch_bounds__(256)
void readout_partial_kernel(const float* __restrict__ W_out)
{
    __shared__ float red[8];

    const int b    = blockIdx.x;
    const int o    = b >> 3;
    const int c    = b & 7;
    const int tid  = threadIdx.x;
    const int lane = tid & 31;
    const int wid  = tid >> 5;

    const int base = c * 1024 + tid * 4;   // element index within the 8192 row
    const float4 w = __ldg(reinterpret_cast<const float4*>(W_out + (size_t)o * DIM_RES + base));
    const float4 v = *reinterpret_cast<const float4*>(g_rnew + base);

    float acc = fmaf(w.x, v.x, fmaf(w.y, v.y, fmaf(w.z, v.z, w.w * v.w)));

    #pragma unroll
    for (int off = 16; off > 0; off >>= 1)
        acc += __shfl_down_sync(0xFFFFFFFFu, acc, off);

    if (lane == 0) red[wid] = acc;
    __syncthreads();

    if (wid == 0) {
        float s = (lane < 8) ? red[lane] : 0.0f;
        #pragma unroll
        for (int off = 4; off > 0; off >>= 1)
            s += __shfl_down_sync(0xFFFFFFFFu, s, off);
        if (lane == 0) g_part[b] = s;
    }
}

// ---------------------------------------------------------------------------
// Kernel 3: combine 8 partials per output. 1 block, 32 threads. Deterministic.
// ---------------------------------------------------------------------------
__global__ void readout_combine_kernel(float* __restrict__ out)
{
    const int o = threadIdx.x;   // 0..31
    float s = 0.0f;
    #pragma unroll
    for (int c = 0; c < 8; ++c)
        s += g_part[o * 8 + c];
    out[o] = s;
}

// ---------------------------------------------------------------------------
extern "C" void kernel_launch(void* const* d_in, const int* in_sizes, int n_in,
                              void* d_out, int out_size)
{
    const float* u      = (const float*)d_in[0];
    const float* W      = (const float*)d_in[1];
    const float* W_in   = (const float*)d_in[2];
    const float* W_fb   = (const float*)d_in[3];
    const float* W_out  = (const float*)d_in[4];
    const float* r      = (const float*)d_in[5];
    const float* y_prev = (const float*)d_in[6];
    float* out = (float*)d_out;

    reservoir_update_kernel<<<DIM_RES / 8, 256>>>(W, W_in, W_fb, r, u, y_prev);
    readout_partial_kernel<<<DIM_OUT * 8, 256>>>(W_out);
    readout_combine_kernel<<<1, 32>>>(out);
}

// round 15
// speedup vs baseline: 1.1842x; 1.1842x over previous
#include <cuda_runtime.h>
#include <math.h>

// Reservoir step:
//   state = W @ r + W_in @ u + W_fb @ y_prev          [8192]
//   r_new = r + (DT/TAU) * (tanh(state) - r)          [8192]
//   out   = W_out @ r_new                             [32]
//
// Inputs (metadata order):
//   d_in[0] input_signal [64]        f32
//   d_in[1] W            [8192*8192] f32
//   d_in[2] W_in         [8192*64]   f32
//   d_in[3] W_fb         [8192*32]   f32
//   d_in[4] W_out        [32*8192]   f32
//   d_in[5] r            [8192]      f32
//   d_in[6] out_prev     [32]        f32
// Output: [32] f32

#define DIM_RES 8192
#define DIM_IN  64
#define DIM_OUT 32
#define LEAK    (0.1f / 10.0f)   // DT / TAU

// scratch between kernels (no cudaMalloc allowed)
__device__ float g_rnew[DIM_RES];
__device__ float g_part[DIM_OUT * 8];   // readout partials: [o][chunk]

// ---------------------------------------------------------------------------
// Kernel 1: fused  state -> tanh -> leaky update -> g_rnew
//
// ROUND-10 POST-MORTEM: occ-7 never materialized (smem rounds to 33 KB ->
// 6 blocks/SM) and BW was Little's-law-limited: ~40 warps/SM x 16 lines with
// ~50% duty ~= 4.6 TB/s measured. Fix = more warps at the SAME 32-reg cost:
// 512-thread blocks -> 4 blocks/SM = 2048 threads = 64 warps/SM (100% occ).
//   smem: 4 x 33 KB = 132 KB < 228 KB.  regs: 64K/2048 = 32 (ptxas already
//   achieves 32 with this body).  grid 512, 16 rows/block, warp-per-row.
// Predicted: 59.7 -> ~40 us (64/40 x 4.6 ~ 7.4 TB/s, HBM-capped).
// ---------------------------------------------------------------------------
__global__ __launch_bounds__(512, 4)
void reservoir_update_kernel(const float* __restrict__ W,
                             const float* __restrict__ W_in,
                             const float* __restrict__ W_fb,
                             const float* __restrict__ r,
                             const float* __restrict__ u,
                             const float* __restrict__ y_prev)
{
    __shared__ float4 sr[DIM_RES / 4];   // 32 KB

    const int tid  = threadIdx.x;
    const int lane = tid & 31;
    const int wid  = tid >> 5;           // 0..15

    // cooperative load of r into shared (coalesced float4)
    const float4* r4 = reinterpret_cast<const float4*>(r);
    #pragma unroll
    for (int t = 0; t < (DIM_RES / 4) / 512; ++t) {
        sr[tid + t * 512] = r4[tid + t * 512];
    }
    __syncthreads();

    const int row = blockIdx.x * 16 + wid;   // 512 blocks * 16 warps = 8192 rows

    const float4* Wrow = reinterpret_cast<const float4*>(W + (size_t)row * DIM_RES);
    float acc = 0.0f;
    #pragma unroll 4
    for (int it = 0; it < (DIM_RES / 4) / 32; ++it) {
        const int idx = it * 32 + lane;          // coalesced 128B per warp-step
        float4 w = __ldg(&Wrow[idx]);
        float4 v = sr[idx];
        acc = fmaf(w.x, v.x, acc);
        acc = fmaf(w.y, v.y, acc);
        acc = fmaf(w.z, v.z, acc);
        acc = fmaf(w.w, v.w, acc);
    }

    // small terms: W_in[row,:] @ u (64) + W_fb[row,:] @ y_prev (32)
    {
        const float* wi = W_in + (size_t)row * DIM_IN;
        const float* wf = W_fb + (size_t)row * DIM_OUT;
        acc = fmaf(__ldg(&wi[lane]),      __ldg(&u[lane]),       acc);
        acc = fmaf(__ldg(&wi[lane + 32]), __ldg(&u[lane + 32]),  acc);
        acc = fmaf(__ldg(&wf[lane]),      __ldg(&y_prev[lane]),  acc);
    }

    #pragma unroll
    for (int off = 16; off > 0; off >>= 1)
        acc += __shfl_down_sync(0xFFFFFFFFu, acc, off);

    if (lane == 0) {
        float rv = reinterpret_cast<const float*>(sr)[row & (DIM_RES - 1)];
        float rn = rv + LEAK * (tanhf(acc) - rv);
        __stcg(&g_rnew[row], rn);    // keep in L2 for the readout
    }
}

// ---------------------------------------------------------------------------
// Kernel 2: readout partials. 256 blocks; block b -> output o=b>>3, chunk c=b&7.
// Each block reduces 1024 elems (1 float4/thread). All SMs active.
// ---------------------------------------------------------------------------
__global__ __launch_bounds__(256)
void readout_partial_kernel(const float* __restrict__ W_out)
{
    __shared__ float red[8];

    const int b    = blockIdx.x;
    const int o    = b >> 3;
    const int c    = b & 7;
    const int tid  = threadIdx.x;
    const int lane = tid & 31;
    const int wid  = tid >> 5;

    const int base = c * 1024 + tid * 4;   // element index within the 8192 row
    const float4 w = __ldg(reinterpret_cast<const float4*>(W_out + (size_t)o * DIM_RES + base));
    const float4 v = *reinterpret_cast<const float4*>(g_rnew + base);

    float acc = fmaf(w.x, v.x, fmaf(w.y, v.y, fmaf(w.z, v.z, w.w * v.w)));

    #pragma unroll
    for (int off = 16; off > 0; off >>= 1)
        acc += __shfl_down_sync(0xFFFFFFFFu, acc, off);

    if (lane == 0) red[wid] = acc;
    __syncthreads();

    if (wid == 0) {
        float s = (lane < 8) ? red[lane] : 0.0f;
        #pragma unroll
        for (int off = 4; off > 0; off >>= 1)
            s += __shfl_down_sync(0xFFFFFFFFu, s, off);
        if (lane == 0) g_part[b] = s;
    }
}

// ---------------------------------------------------------------------------
// Kernel 3: combine 8 partials per output. 1 block, 32 threads. Deterministic.
// ---------------------------------------------------------------------------
__global__ void readout_combine_kernel(float* __restrict__ out)
{
    const int o = threadIdx.x;   // 0..31
    float s = 0.0f;
    #pragma unroll
    for (int c = 0; c < 8; ++c)
        s += g_part[o * 8 + c];
    out[o] = s;
}

// ---------------------------------------------------------------------------
extern "C" void kernel_launch(void* const* d_in, const int* in_sizes, int n_in,
                              void* d_out, int out_size)
{
    const float* u      = (const float*)d_in[0];
    const float* W      = (const float*)d_in[1];
    const float* W_in   = (const float*)d_in[2];
    const float* W_fb   = (const float*)d_in[3];
    const float* W_out  = (const float*)d_in[4];
    const float* r      = (const float*)d_in[5];
    const float* y_prev = (const float*)d_in[6];
    float* out = (float*)d_out;

    reservoir_update_kernel<<<DIM_RES / 16, 512>>>(W, W_in, W_fb, r, u, y_prev);
    readout_partial_kernel<<<DIM_OUT * 8, 256>>>(W_out);
    readout_combine_kernel<<<1, 32>>>(out);
}

// round 17
// speedup vs baseline: 1.1856x; 1.0012x over previous
#include <cuda_runtime.h>
#include <math.h>

// Reservoir step:
//   state = W @ r + W_in @ u + W_fb @ y_prev          [8192]
//   r_new = r + (DT/TAU) * (tanh(state) - r)          [8192]
//   out   = W_out @ r_new                             [32]
//
// Inputs (metadata order):
//   d_in[0] input_signal [64]        f32
//   d_in[1] W            [8192*8192] f32
//   d_in[2] W_in         [8192*64]   f32
//   d_in[3] W_fb         [8192*32]   f32
//   d_in[4] W_out        [32*8192]   f32
//   d_in[5] r            [8192]      f32
//   d_in[6] out_prev     [32]        f32
// Output: [32] f32

#define DIM_RES 8192
#define DIM_IN  64
#define DIM_OUT 32
#define LEAK    (0.1f / 10.0f)   // DT / TAU
#define GRID1   592              // 148 SMs x 4 blocks -> EXACTLY 4 blocks/SM

// scratch between kernels (no cudaMalloc allowed)
__device__ float g_rnew[DIM_RES];
__device__ float g_part[DIM_OUT * 8];   // readout partials: [o][chunk]

// ---------------------------------------------------------------------------
// Kernel 1: fused  state -> tanh -> leaky update -> g_rnew
//
// R15 POST-MORTEM: 50.8us @ 5.42 TB/s, occ 79.4%. BW scales with resident
// warps (R10: 40w->4.6, R15: 51w->5.42 TB/s). Grid 512 @ 4 blk/SM put 4
// blocks on 68 SMs and 3 on 80 -> heavy SMs are a ~16% critical path.
// FIX (one delta): grid 592 = 148x4, row = wid*592 + b.
// Every SM gets exactly 4 blocks; active warps per block are identical
// (w 0..12 full, w13 partial for b<496, w14-15 idle) -> ~55.4 streaming
// warps on EVERY SM. Per-warp code, smem staging, regs unchanged.
// Predicted: kernel1 50.8 -> 44-46 us, HBM -> ~6.2 TB/s.
// ---------------------------------------------------------------------------
__global__ __launch_bounds__(512, 4)
void reservoir_update_kernel(const float* __restrict__ W,
                             const float* __restrict__ W_in,
                             const float* __restrict__ W_fb,
                             const float* __restrict__ r,
                             const float* __restrict__ u,
                             const float* __restrict__ y_prev)
{
    __shared__ float4 sr[DIM_RES / 4];   // 32 KB

    const int tid  = threadIdx.x;
    const int lane = tid & 31;
    const int wid  = tid >> 5;           // 0..15

    // cooperative load of r into shared (coalesced float4)
    const float4* r4 = reinterpret_cast<const float4*>(r);
    #pragma unroll
    for (int t = 0; t < (DIM_RES / 4) / 512; ++t) {
        sr[tid + t * 512] = r4[tid + t * 512];
    }
    __syncthreads();

    // balanced row mapping: every block has the same active-warp shape
    const int row = wid * GRID1 + blockIdx.x;
    if (row >= DIM_RES) return;          // warps 14,15 (and part of 13) idle

    const float4* Wrow = reinterpret_cast<const float4*>(W + (size_t)row * DIM_RES);
    float acc = 0.0f;
    #pragma unroll 4
    for (int it = 0; it < (DIM_RES / 4) / 32; ++it) {
        const int idx = it * 32 + lane;          // coalesced 128B per warp-step
        float4 w = __ldg(&Wrow[idx]);
        float4 v = sr[idx];
        acc = fmaf(w.x, v.x, acc);
        acc = fmaf(w.y, v.y, acc);
        acc = fmaf(w.z, v.z, acc);
        acc = fmaf(w.w, v.w, acc);
    }

    // small terms: W_in[row,:] @ u (64) + W_fb[row,:] @ y_prev (32)
    {
        const float* wi = W_in + (size_t)row * DIM_IN;
        const float* wf = W_fb + (size_t)row * DIM_OUT;
        acc = fmaf(__ldg(&wi[lane]),      __ldg(&u[lane]),       acc);
        acc = fmaf(__ldg(&wi[lane + 32]), __ldg(&u[lane + 32]),  acc);
        acc = fmaf(__ldg(&wf[lane]),      __ldg(&y_prev[lane]),  acc);
    }

    #pragma unroll
    for (int off = 16; off > 0; off >>= 1)
        acc += __shfl_down_sync(0xFFFFFFFFu, acc, off);

    if (lane == 0) {
        float rv = reinterpret_cast<const float*>(sr)[row & (DIM_RES - 1)];
        float rn = rv + LEAK * (tanhf(acc) - rv);
        __stcg(&g_rnew[row], rn);    // keep in L2 for the readout
    }
}

// ---------------------------------------------------------------------------
// Kernel 2: readout partials. 256 blocks; block b -> output o=b>>3, chunk c=b&7.
// Each block reduces 1024 elems (1 float4/thread). All SMs active.
// ---------------------------------------------------------------------------
__global__ __launch_bounds__(256)
void readout_partial_kernel(const float* __restrict__ W_out)
{
    __shared__ float red[8];

    const int b    = blockIdx.x;
    const int o    = b >> 3;
    const int c    = b & 7;
    const int tid  = threadIdx.x;
    const int lane = tid & 31;
    const int wid  = tid >> 5;

    const int base = c * 1024 + tid * 4;   // element index within the 8192 row
    const float4 w = __ldg(reinterpret_cast<const float4*>(W_out + (size_t)o * DIM_RES + base));
    const float4 v = *reinterpret_cast<const float4*>(g_rnew + base);

    float acc = fmaf(w.x, v.x, fmaf(w.y, v.y, fmaf(w.z, v.z, w.w * v.w)));

    #pragma unroll
    for (int off = 16; off > 0; off >>= 1)
        acc += __shfl_down_sync(0xFFFFFFFFu, acc, off);

    if (lane == 0) red[wid] = acc;
    __syncthreads();

    if (wid == 0) {
        float s = (lane < 8) ? red[lane] : 0.0f;
        #pragma unroll
        for (int off = 4; off > 0; off >>= 1)
            s += __shfl_down_sync(0xFFFFFFFFu, s, off);
        if (lane == 0) g_part[b] = s;
    }
}

// ---------------------------------------------------------------------------
// Kernel 3: combine 8 partials per output. 1 block, 32 threads. Deterministic.
// ---------------------------------------------------------------------------
__global__ void readout_combine_kernel(float* __restrict__ out)
{
    const int o = threadIdx.x;   // 0..31
    float s = 0.0f;
    #pragma unroll
    for (int c = 0; c < 8; ++c)
        s += g_part[o * 8 + c];
    out[o] = s;
}

// ---------------------------------------------------------------------------
extern "C" void kernel_launch(void* const* d_in, const int* in_sizes, int n_in,
                              void* d_out, int out_size)
{
    const float* u      = (const float*)d_in[0];
    const float* W      = (const float*)d_in[1];
    const float* W_in   = (const float*)d_in[2];
    const float* W_fb   = (const float*)d_in[3];
    const float* W_out  = (const float*)d_in[4];
    const float* r      = (const float*)d_in[5];
    const float* y_prev = (const float*)d_in[6];
    float* out = (float*)d_out;

    reservoir_update_kernel<<<GRID1, 512>>>(W, W_in, W_fb, r, u, y_prev);
    readout_partial_kernel<<<DIM_OUT * 8, 256>>>(W_out);
    readout_combine_kernel<<<1, 32>>>(out);
}